// round 7
// baseline (speedup 1.0000x reference)
#include <cuda_runtime.h>
#include <cuda_bf16.h>
#include <cstdint>

#define NTR 8192
#define NT  8192
#define DIN 1024
#define LD  64
#define DY  128

// ---------------------------------------------------------------------------
// device scratch (no allocations allowed)
// ---------------------------------------------------------------------------
__device__ float g_Q[(size_t)NT * LD];
__device__ float g_K[(size_t)NTR * LD];
__device__ float g_muA[LD];
__device__ __nv_bfloat16 g_Ah[(size_t)DIN * LD];
__device__ __nv_bfloat16 g_Al[(size_t)DIN * LD];
__device__ __nv_bfloat16 g_Qh[(size_t)NT * LD];
__device__ __nv_bfloat16 g_Ql[(size_t)NT * LD];
__device__ __nv_bfloat16 g_Kh[(size_t)NTR * LD];
__device__ __nv_bfloat16 g_Kl[(size_t)NTR * LD];
__device__ __nv_bfloat16 g_Vh[(size_t)NTR * DY];
__device__ __nv_bfloat16 g_Vl[(size_t)NTR * DY];
__device__ float g_Opart[2 * (size_t)NT * DY];
__device__ float g_lpart[2 * (size_t)NT];

// ---------------------------------------------------------------------------
// helpers (portable PTX only: sm_80-level mma/ldmatrix/cp.async)
// ---------------------------------------------------------------------------
__device__ __forceinline__ uint32_t smem_u32(const void* p) {
    uint32_t a;
    asm("{ .reg .u64 t; cvta.to.shared.u64 t, %1; cvt.u32.u64 %0, t; }"
        : "=r"(a) : "l"(p));
    return a;
}

__device__ __forceinline__ void cp16(uint32_t dst, const void* src) {
    asm volatile("cp.async.cg.shared.global [%0], [%1], 16;"
                 :: "r"(dst), "l"(src));
}
#define CP_COMMIT asm volatile("cp.async.commit_group;" ::: "memory")
#define CP_WAIT0  asm volatile("cp.async.wait_group 0;" ::: "memory")

__device__ __forceinline__ void ldsm_x4(uint32_t* r, uint32_t a) {
    asm volatile("ldmatrix.sync.aligned.m8n8.x4.shared.b16 {%0,%1,%2,%3}, [%4];"
                 : "=r"(r[0]), "=r"(r[1]), "=r"(r[2]), "=r"(r[3]) : "r"(a));
}
__device__ __forceinline__ void ldsm_x4t(uint32_t* r, uint32_t a) {
    asm volatile("ldmatrix.sync.aligned.m8n8.x4.trans.shared.b16 {%0,%1,%2,%3}, [%4];"
                 : "=r"(r[0]), "=r"(r[1]), "=r"(r[2]), "=r"(r[3]) : "r"(a));
}
__device__ __forceinline__ void mma_bf16(float* c, const uint32_t* a,
                                         uint32_t b0, uint32_t b1) {
    asm volatile(
        "mma.sync.aligned.m16n8k16.row.col.f32.bf16.bf16.f32 "
        "{%0,%1,%2,%3}, {%4,%5,%6,%7}, {%8,%9}, {%0,%1,%2,%3};"
        : "+f"(c[0]), "+f"(c[1]), "+f"(c[2]), "+f"(c[3])
        : "r"(a[0]), "r"(a[1]), "r"(a[2]), "r"(a[3]), "r"(b0), "r"(b1));
}

__device__ __forceinline__ uint32_t pack_bf16(float a, float b) {
    const unsigned short ha = __bfloat16_as_ushort(__float2bfloat16(a));
    const unsigned short hb = __bfloat16_as_ushort(__float2bfloat16(b));
    return (uint32_t)ha | ((uint32_t)hb << 16);
}
__device__ __forceinline__ float bf_hi_res(float v, float& res) {
    const __nv_bfloat16 h = __float2bfloat16(v);
    res = v - __bfloat162float(h);
    return __bfloat162float(h);
}

// ---------------------------------------------------------------------------
// A split: A[1024,64] f32 -> g_Ah/g_Al bf16
// ---------------------------------------------------------------------------
__global__ __launch_bounds__(256) void asplit_kernel(const float* __restrict__ A) {
    const int i = blockIdx.x * 256 + threadIdx.x;  // float4 idx, 16384 total
    float4 v = ((const float4*)A)[i];
    float r0, r1, r2, r3;
    const float h0 = bf_hi_res(v.x, r0), h1 = bf_hi_res(v.y, r1);
    const float h2 = bf_hi_res(v.z, r2), h3 = bf_hi_res(v.w, r3);
    uint2 ph, pl;
    ph.x = pack_bf16(h0, h1); ph.y = pack_bf16(h2, h3);
    pl.x = pack_bf16(r0, r1); pl.y = pack_bf16(r2, r3);
    ((uint2*)g_Ah)[i] = ph;
    ((uint2*)g_Al)[i] = pl;
}

// ---------------------------------------------------------------------------
// Tensor-core projection: C[8192,64] = X[8192,1024] @ A[1024,64]
// 128 CTAs x 256 threads; M=128 rows/CTA; X split to bf16 hi/lo on the fly.
// 3-term: Xh*Ah + Xl*Ah + Xh*Al.
// ---------------------------------------------------------------------------
__global__ __launch_bounds__(256) void proj_tc_kernel(const float* __restrict__ xtr,
                                                      const float* __restrict__ xt) {
    __shared__ __align__(1024) char psm[49152];  // Xh 16K | Xl 16K | Ah 8K | Al 8K
    const uint32_t sb = smem_u32(psm);
    const uint32_t sbXh = sb, sbAh = sb + 32768;

    const bool isQ = (blockIdx.x >= 64);
    const float* __restrict__ X = isQ ? xt : xtr;
    float* C = isQ ? g_Q : g_K;
    const int mbase = (blockIdx.x & 63) * 128;

    const int tid = threadIdx.x;
    const int wid = tid >> 5;
    const int lane = tid & 31;
    const int l7 = lane & 7, l15 = lane & 15;
    const int g = lane >> 2, t = lane & 3;
    const int ab = lane >> 3;
    const int arow = l7 + ((ab & 1) << 3);
    const int acs = ab >> 1;
    const int nn_inc = (lane >> 4) & 1;
    const int wr = wid * 16;

    float oacc[8][4];
#pragma unroll
    for (int n = 0; n < 8; ++n)
#pragma unroll
        for (int j = 0; j < 4; ++j) oacc[n][j] = 0.0f;

    for (int kt = 0; kt < 16; ++kt) {
        const int k0 = kt * 64;
        // A tiles via cp.async (64 rows x 8 chunks, swizzled 128B rows)
        for (int c = tid; c < 512; c += 256) {
            const int k = c >> 3, dc = c & 7;
            const uint32_t swo = (uint32_t)(k * 128 + ((dc ^ (k & 7)) << 4));
            cp16(sbAh + swo, g_Ah + (size_t)(k0 + k) * LD + dc * 8);
            cp16(sbAh + 8192 + swo, g_Al + (size_t)(k0 + k) * LD + dc * 8);
        }
        CP_COMMIT;
        // X tile: load f32, split, store bf16 hi/lo (swizzled 128B rows)
        for (int c = tid; c < 1024; c += 256) {
            const int row = c >> 3, dc = c & 7;
            const float* src = X + (size_t)(mbase + row) * DIN + k0 + dc * 8;
            const float4 v0 = *(const float4*)src;
            const float4 v1 = *(const float4*)(src + 4);
            float r0, r1, r2, r3, r4, r5, r6, r7;
            const float h0 = bf_hi_res(v0.x, r0), h1 = bf_hi_res(v0.y, r1);
            const float h2 = bf_hi_res(v0.z, r2), h3 = bf_hi_res(v0.w, r3);
            const float h4 = bf_hi_res(v1.x, r4), h5 = bf_hi_res(v1.y, r5);
            const float h6 = bf_hi_res(v1.z, r6), h7 = bf_hi_res(v1.w, r7);
            uint4 ph, pl;
            ph.x = pack_bf16(h0, h1); ph.y = pack_bf16(h2, h3);
            ph.z = pack_bf16(h4, h5); ph.w = pack_bf16(h6, h7);
            pl.x = pack_bf16(r0, r1); pl.y = pack_bf16(r2, r3);
            pl.z = pack_bf16(r4, r5); pl.w = pack_bf16(r6, r7);
            const uint32_t swo = (uint32_t)(row * 128 + ((dc ^ (row & 7)) << 4));
            *(uint4*)(psm + swo) = ph;
            *(uint4*)(psm + 16384 + swo) = pl;
        }
        CP_WAIT0;
        __syncthreads();

        const uint32_t xa_base = sbXh + (uint32_t)((wr + arow) * 128);
#pragma unroll
        for (int ks = 0; ks < 4; ++ks) {
            uint32_t axh[4], axl[4];
            const uint32_t qaddr = xa_base + (uint32_t)((((ks << 1) + acs) ^ l7) << 4);
            ldsm_x4(axh, qaddr);
            ldsm_x4(axl, qaddr + 16384);
            const uint32_t brow = sbAh + (uint32_t)((ks * 16 + l15) * 128);
#pragma unroll
            for (int n = 0; n < 8; n += 2) {
                const uint32_t baddr = brow + (uint32_t)(((n + nn_inc) ^ l7) << 4);
                uint32_t bh[4], bl[4];
                ldsm_x4t(bh, baddr);
                ldsm_x4t(bl, baddr + 8192);
                mma_bf16(oacc[n], axh, bh[0], bh[1]);
                mma_bf16(oacc[n], axl, bh[0], bh[1]);
                mma_bf16(oacc[n], axh, bl[0], bl[1]);
                mma_bf16(oacc[n + 1], axh, bh[2], bh[3]);
                mma_bf16(oacc[n + 1], axl, bh[2], bh[3]);
                mma_bf16(oacc[n + 1], axh, bl[2], bl[3]);
            }
        }
        __syncthreads();
    }

    const int row0 = mbase + wr + g;
#pragma unroll
    for (int n = 0; n < 8; ++n) {
        *(float2*)(C + (size_t)row0 * LD + n * 8 + 2 * t) =
            make_float2(oacc[n][0], oacc[n][1]);
        *(float2*)(C + (size_t)(row0 + 8) * LD + n * 8 + 2 * t) =
            make_float2(oacc[n][2], oacc[n][3]);
    }
}

// ---------------------------------------------------------------------------
__global__ __launch_bounds__(256) void colmean_kernel() {
    __shared__ float red[256];
    const int l = blockIdx.x;
    float s = 0.0f;
    for (int r = threadIdx.x; r < NTR; r += 256) s += g_K[(size_t)r * LD + l];
    red[threadIdx.x] = s;
    __syncthreads();
    for (int off = 128; off > 0; off >>= 1) {
        if (threadIdx.x < off) red[threadIdx.x] += red[threadIdx.x + off];
        __syncthreads();
    }
    if (threadIdx.x == 0) g_muA[l] = red[0] * (1.0f / (float)NTR);
}

// ---------------------------------------------------------------------------
// center + bf16 split of Q/K
// ---------------------------------------------------------------------------
__global__ __launch_bounds__(256) void split_qk_kernel() {
    int i = blockIdx.x * 256 + threadIdx.x;      // 0..262143 float4 elems
    const bool isQ = (i >= 131072);
    const float* src = isQ ? g_Q : g_K;
    __nv_bfloat16* dh = isQ ? g_Qh : g_Kh;
    __nv_bfloat16* dl = isQ ? g_Ql : g_Kl;
    const int j = isQ ? i - 131072 : i;
    float4 v = ((const float4*)src)[j];
    const int l = (j * 4) & 63;
    v.x -= g_muA[l + 0];
    v.y -= g_muA[l + 1];
    v.z -= g_muA[l + 2];
    v.w -= g_muA[l + 3];
    float r0, r1, r2, r3;
    const float h0 = bf_hi_res(v.x, r0), h1 = bf_hi_res(v.y, r1);
    const float h2 = bf_hi_res(v.z, r2), h3 = bf_hi_res(v.w, r3);
    uint2 ph, pl;
    ph.x = pack_bf16(h0, h1); ph.y = pack_bf16(h2, h3);
    pl.x = pack_bf16(r0, r1); pl.y = pack_bf16(r2, r3);
    ((uint2*)dh)[j] = ph;
    ((uint2*)dl)[j] = pl;
}

// ---------------------------------------------------------------------------
// V split (keeps [key][dy] layout): ytr [8192,128] f32 -> Vh/Vl bf16
// ---------------------------------------------------------------------------
__global__ __launch_bounds__(256) void vsplit_kernel(const float* __restrict__ ytr) {
    const int i = blockIdx.x * 256 + threadIdx.x;  // float4 idx, 262144 total
    float4 v = ((const float4*)ytr)[i];
    float r0, r1, r2, r3;
    const float h0 = bf_hi_res(v.x, r0), h1 = bf_hi_res(v.y, r1);
    const float h2 = bf_hi_res(v.z, r2), h3 = bf_hi_res(v.w, r3);
    uint2 ph, pl;
    ph.x = pack_bf16(h0, h1); ph.y = pack_bf16(h2, h3);
    pl.x = pack_bf16(r0, r1); pl.y = pack_bf16(r2, r3);
    ((uint2*)g_Vh)[i] = ph;
    ((uint2*)g_Vl)[i] = pl;
}

// ---------------------------------------------------------------------------
// flash kernel: mma.sync bf16, double-buffered cp.async, x4 ldmatrix.
// 128 CTAs = 64 qblks x 2 key-halves; 256 threads = 8 warps x 16 query rows.
// smem: Q hi/lo 32KB + 2 x (K 32KB + V 64KB) = 224KB
// ---------------------------------------------------------------------------
#define FB_QH 0
#define FB_QL 16384
#define FB_BUF0 32768
#define FB_BUFSZ 98304
// within buffer: KH +0, KL +16384, VH +32768, VL +65536
#define FSM_BYTES (32768 + 2 * 98304)

extern __shared__ char fsm[];

__device__ __forceinline__ void flash_load_tile(uint32_t sb, int buf, int kb, int tid) {
    const uint32_t base = sb + FB_BUF0 + (uint32_t)buf * FB_BUFSZ;
    for (int c = tid; c < 1024; c += 256) {
        const int key = c >> 3, dc = c & 7;
        const uint32_t dst = base + key * 128 + ((dc ^ (key & 7)) << 4);
        const size_t gk = ((size_t)(kb + key) << 6) + dc * 8;
        cp16(dst, g_Kh + gk);
        cp16(dst + 16384, g_Kl + gk);
    }
    for (int c = tid; c < 2048; c += 256) {
        const int key = c >> 4, dc = c & 15;
        const uint32_t dst = base + 32768 + key * 256 + ((dc ^ (key & 7)) << 4);
        const size_t gv = ((size_t)(kb + key) << 7) + dc * 8;
        cp16(dst, g_Vh + gv);
        cp16(dst + 32768, g_Vl + gv);
    }
}

__global__ __launch_bounds__(256) void flash_mma_kernel() {
    const int tid = threadIdx.x;
    const int wid = tid >> 5;
    const int lane = tid & 31;
    const int g = lane >> 2;
    const int t = lane & 3;
    const int qblk = blockIdx.x >> 1;
    const int half = blockIdx.x & 1;
    const int qbase = qblk * 128;
    const int wr = wid * 16;
    const uint32_t sb = smem_u32(fsm);

    // ---- Q tile load (once) + tile 0 prefetch, one cp group
    for (int c = tid; c < 1024; c += 256) {
        const int row = c >> 3, dc = c & 7;
        const uint32_t dst = sb + FB_QH + row * 128 + ((dc ^ (row & 7)) << 4);
        const size_t gq = ((size_t)(qbase + row) << 6) + dc * 8;
        cp16(dst, g_Qh + gq);
        cp16(dst + (FB_QL - FB_QH), g_Ql + gq);
    }
    flash_load_tile(sb, 0, half * 4096, tid);
    CP_COMMIT;

    // per-lane ldmatrix address components
    const int l7 = lane & 7, l15 = lane & 15;
    const int ab = lane >> 3;
    const int arow = l7 + ((ab & 1) << 3);
    const int acs = ab >> 1;
    const int kcb = (lane >> 3) & 1;       // chunk bit pattern (0,1,0,1 per 8 lanes)
    const int nn_inc = (lane >> 4) & 1;    // second-tile bit for x4 loads
    const uint32_t qa_base = sb + FB_QH + (uint32_t)(wr + arow) * 128;

    float oacc[16][4];
#pragma unroll
    for (int n = 0; n < 16; ++n)
#pragma unroll
        for (int j = 0; j < 4; ++j) oacc[n][j] = 0.0f;
    float rlo = 0.0f, rhi = 0.0f;

    for (int jt = 0; jt < 32; ++jt) {
        const int cur = jt & 1;
        const uint32_t bbase = sb + FB_BUF0 + (uint32_t)cur * FB_BUFSZ;

        CP_WAIT0;
        __syncthreads();
        if (jt + 1 < 32) {
            flash_load_tile(sb, cur ^ 1, (half * 32 + jt + 1) * 128, tid);
            CP_COMMIT;
        }

        // ---- S = Q K^T : 8 x4-ldmatrix pairs per ks, 3 split terms
        float sacc[16][4];
#pragma unroll
        for (int n = 0; n < 16; ++n)
#pragma unroll
            for (int j = 0; j < 4; ++j) sacc[n][j] = 0.0f;

#pragma unroll
        for (int ks = 0; ks < 4; ++ks) {
            uint32_t aqh[4], aql[4];
            const uint32_t qaddr =
                qa_base + (uint32_t)((((ks << 1) + acs) ^ l7) << 4);
            ldsm_x4(aqh, qaddr);
            ldsm_x4(aql, qaddr + (FB_QL - FB_QH));
            const uint32_t ksw = (uint32_t)((((ks << 1) + kcb) ^ l7) << 4);
#pragma unroll
            for (int n = 0; n < 16; n += 2) {
                const uint32_t kaddr =
                    bbase + (uint32_t)((((n + nn_inc) << 3) + l7) * 128) + ksw;
                uint32_t bh[4], bl[4];
                ldsm_x4(bh, kaddr);
                ldsm_x4(bl, kaddr + 16384);
                mma_bf16(sacc[n], aqh, bh[0], bh[1]);
                mma_bf16(sacc[n], aql, bh[0], bh[1]);
                mma_bf16(sacc[n], aqh, bl[0], bl[1]);
                mma_bf16(sacc[n + 1], aqh, bh[2], bh[3]);
                mma_bf16(sacc[n + 1], aql, bh[2], bh[3]);
                mma_bf16(sacc[n + 1], aqh, bl[2], bl[3]);
            }
        }

        // ---- P = exp(S), pack in-register into A-fragments (hi + lo)
        uint32_t ph[16][2], pl[16][2];
#pragma unroll
        for (int n = 0; n < 16; ++n) {
            const float e0 = __expf(sacc[n][0]);
            const float e1 = __expf(sacc[n][1]);
            const float e2 = __expf(sacc[n][2]);
            const float e3 = __expf(sacc[n][3]);
            rlo += e0 + e1;
            rhi += e2 + e3;
            float r0, r1, r2, r3;
            const float h0 = bf_hi_res(e0, r0), h1 = bf_hi_res(e1, r1);
            const float h2 = bf_hi_res(e2, r2), h3 = bf_hi_res(e3, r3);
            ph[n][0] = pack_bf16(h0, h1);
            ph[n][1] = pack_bf16(h2, h3);
            pl[n][0] = pack_bf16(r0, r1);
            pl[n][1] = pack_bf16(r2, r3);
        }

        // ---- O += P V : x4 trans V loads, 3 split terms
        const uint32_t va_base = bbase + 32768 + (uint32_t)l15 * 256;
#pragma unroll
        for (int s = 0; s < 8; ++s) {
            const uint32_t ah[4] = {ph[2 * s][0], ph[2 * s][1],
                                    ph[2 * s + 1][0], ph[2 * s + 1][1]};
            const uint32_t al[4] = {pl[2 * s][0], pl[2 * s][1],
                                    pl[2 * s + 1][0], pl[2 * s + 1][1]};
            const uint32_t vsb = va_base + (uint32_t)(s << 12);
#pragma unroll
            for (int n = 0; n < 16; n += 2) {
                const uint32_t vaddr = vsb + (uint32_t)(((n + nn_inc) ^ l7) << 4);
                uint32_t vh[4], vl[4];
                ldsm_x4t(vh, vaddr);
                ldsm_x4t(vl, vaddr + 32768);
                mma_bf16(oacc[n], ah, vh[0], vh[1]);
                mma_bf16(oacc[n], al, vh[0], vh[1]);
                mma_bf16(oacc[n], ah, vl[0], vl[1]);
                mma_bf16(oacc[n + 1], ah, vh[2], vh[3]);
                mma_bf16(oacc[n + 1], al, vh[2], vh[3]);
                mma_bf16(oacc[n + 1], ah, vl[2], vl[3]);
            }
        }
    }

    // ---- write unnormalized partial O
    float* Op = g_Opart + (size_t)half * NT * DY;
    const int row0 = qbase + wr + g;
#pragma unroll
    for (int n = 0; n < 16; ++n) {
        *(float2*)(Op + (size_t)row0 * DY + n * 8 + 2 * t) =
            make_float2(oacc[n][0], oacc[n][1]);
        *(float2*)(Op + (size_t)(row0 + 8) * DY + n * 8 + 2 * t) =
            make_float2(oacc[n][2], oacc[n][3]);
    }
    // ---- row-sum partials (reduce over the 4 lanes of each row group)
    rlo += __shfl_xor_sync(0xffffffffu, rlo, 1);
    rlo += __shfl_xor_sync(0xffffffffu, rlo, 2);
    rhi += __shfl_xor_sync(0xffffffffu, rhi, 1);
    rhi += __shfl_xor_sync(0xffffffffu, rhi, 2);
    if (t == 0) {
        g_lpart[(size_t)half * NT + row0] = rlo;
        g_lpart[(size_t)half * NT + row0 + 8] = rhi;
    }
}

// ---------------------------------------------------------------------------
// combine: out = (O0 + O1) / (l0 + l1)
// ---------------------------------------------------------------------------
__global__ __launch_bounds__(256) void combine_kernel(float* __restrict__ out) {
    const int i = blockIdx.x * 256 + threadIdx.x;  // float4 index, 262144 total
    const int r = (i * 4) >> 7;                    // query row
    const float inv = 1.0f / (g_lpart[r] + g_lpart[NT + r]);
    float4 a = ((const float4*)g_Opart)[i];
    float4 b = ((const float4*)(g_Opart + (size_t)NT * DY))[i];
    ((float4*)out)[i] = make_float4((a.x + b.x) * inv, (a.y + b.y) * inv,
                                    (a.z + b.z) * inv, (a.w + b.w) * inv);
}

// ---------------------------------------------------------------------------
extern "C" void kernel_launch(void* const* d_in, const int* in_sizes, int n_in,
                              void* d_out, int out_size) {
    const float* xtr = (const float*)d_in[0];
    const float* ytr = (const float*)d_in[1];
    const float* xt  = (const float*)d_in[2];
    const float* A   = (const float*)d_in[3];
    float* out = (float*)d_out;

    cudaFuncSetAttribute(flash_mma_kernel,
                         cudaFuncAttributeMaxDynamicSharedMemorySize, FSM_BYTES);

    asplit_kernel<<<64, 256>>>(A);
    proj_tc_kernel<<<128, 256>>>(xtr, xt);
    colmean_kernel<<<64, 256>>>();
    split_qk_kernel<<<1024, 256>>>();
    vsplit_kernel<<<1024, 256>>>(ytr);
    flash_mma_kernel<<<128, 256, FSM_BYTES>>>();
    combine_kernel<<<1024, 256>>>(out);
}

// round 8
// speedup vs baseline: 1.1749x; 1.1749x over previous
#include <cuda_runtime.h>
#include <cuda_bf16.h>
#include <cstdint>

#define NTR 8192
#define NT  8192
#define DIN 1024
#define LD  64
#define DY  128

// ---------------------------------------------------------------------------
// device scratch (no allocations allowed)
// ---------------------------------------------------------------------------
__device__ float g_Q[(size_t)NT * LD];
__device__ float g_K[(size_t)NTR * LD];
__device__ float g_muA[LD];
__device__ __nv_bfloat16 g_Ah[(size_t)DIN * LD];
__device__ __nv_bfloat16 g_Al[(size_t)DIN * LD];
__device__ __nv_bfloat16 g_Qh[(size_t)NT * LD];
__device__ __nv_bfloat16 g_Ql[(size_t)NT * LD];
__device__ __nv_bfloat16 g_Kh[(size_t)NTR * LD];
__device__ __nv_bfloat16 g_Kl[(size_t)NTR * LD];
__device__ __nv_bfloat16 g_Vh[(size_t)NTR * DY];
__device__ __nv_bfloat16 g_Vl[(size_t)NTR * DY];
__device__ float g_Opart[2 * (size_t)NT * DY];
__device__ float g_lpart[2 * (size_t)NT];

// ---------------------------------------------------------------------------
// helpers (portable PTX only: sm_80-level mma/ldmatrix/cp.async)
// ---------------------------------------------------------------------------
__device__ __forceinline__ uint32_t smem_u32(const void* p) {
    uint32_t a;
    asm("{ .reg .u64 t; cvta.to.shared.u64 t, %1; cvt.u32.u64 %0, t; }"
        : "=r"(a) : "l"(p));
    return a;
}

__device__ __forceinline__ void cp16(uint32_t dst, const void* src) {
    asm volatile("cp.async.cg.shared.global [%0], [%1], 16;"
                 :: "r"(dst), "l"(src));
}
#define CP_COMMIT asm volatile("cp.async.commit_group;" ::: "memory")
#define CP_WAIT0  asm volatile("cp.async.wait_group 0;" ::: "memory")
#define CP_WAIT1  asm volatile("cp.async.wait_group 1;" ::: "memory")

__device__ __forceinline__ void ldsm_x4(uint32_t* r, uint32_t a) {
    asm volatile("ldmatrix.sync.aligned.m8n8.x4.shared.b16 {%0,%1,%2,%3}, [%4];"
                 : "=r"(r[0]), "=r"(r[1]), "=r"(r[2]), "=r"(r[3]) : "r"(a));
}
__device__ __forceinline__ void ldsm_x2(uint32_t& r0, uint32_t& r1, uint32_t a) {
    asm volatile("ldmatrix.sync.aligned.m8n8.x2.shared.b16 {%0,%1}, [%2];"
                 : "=r"(r0), "=r"(r1) : "r"(a));
}
__device__ __forceinline__ void ldsm_x2t(uint32_t& r0, uint32_t& r1, uint32_t a) {
    asm volatile("ldmatrix.sync.aligned.m8n8.x2.trans.shared.b16 {%0,%1}, [%2];"
                 : "=r"(r0), "=r"(r1) : "r"(a));
}
__device__ __forceinline__ void ldsm_x4t(uint32_t* r, uint32_t a) {
    asm volatile("ldmatrix.sync.aligned.m8n8.x4.trans.shared.b16 {%0,%1,%2,%3}, [%4];"
                 : "=r"(r[0]), "=r"(r[1]), "=r"(r[2]), "=r"(r[3]) : "r"(a));
}
__device__ __forceinline__ void mma_bf16(float* c, const uint32_t* a,
                                         uint32_t b0, uint32_t b1) {
    asm volatile(
        "mma.sync.aligned.m16n8k16.row.col.f32.bf16.bf16.f32 "
        "{%0,%1,%2,%3}, {%4,%5,%6,%7}, {%8,%9}, {%0,%1,%2,%3};"
        : "+f"(c[0]), "+f"(c[1]), "+f"(c[2]), "+f"(c[3])
        : "r"(a[0]), "r"(a[1]), "r"(a[2]), "r"(a[3]), "r"(b0), "r"(b1));
}

__device__ __forceinline__ uint32_t pack_bf16(float a, float b) {
    const unsigned short ha = __bfloat16_as_ushort(__float2bfloat16(a));
    const unsigned short hb = __bfloat16_as_ushort(__float2bfloat16(b));
    return (uint32_t)ha | ((uint32_t)hb << 16);
}
__device__ __forceinline__ float bf_hi_res(float v, float& res) {
    const __nv_bfloat16 h = __float2bfloat16(v);
    res = v - __bfloat162float(h);
    return __bfloat162float(h);
}

// ---------------------------------------------------------------------------
// A split: A[1024,64] f32 -> g_Ah/g_Al bf16
// ---------------------------------------------------------------------------
__global__ __launch_bounds__(256) void asplit_kernel(const float* __restrict__ A) {
    const int i = blockIdx.x * 256 + threadIdx.x;  // float4 idx, 16384 total
    float4 v = ((const float4*)A)[i];
    float r0, r1, r2, r3;
    const float h0 = bf_hi_res(v.x, r0), h1 = bf_hi_res(v.y, r1);
    const float h2 = bf_hi_res(v.z, r2), h3 = bf_hi_res(v.w, r3);
    uint2 ph, pl;
    ph.x = pack_bf16(h0, h1); ph.y = pack_bf16(h2, h3);
    pl.x = pack_bf16(r0, r1); pl.y = pack_bf16(r2, r3);
    ((uint2*)g_Ah)[i] = ph;
    ((uint2*)g_Al)[i] = pl;
}

// ---------------------------------------------------------------------------
// Tensor-core projection, pipelined: C[8192,64] = X[8192,1024] @ A[1024,64]
// 128 CTAs x 256 threads; 128 rows/CTA; X f32 prefetched into registers for
// the next k-tile while current tile computes; A double-buffered via cp.async.
// ---------------------------------------------------------------------------
__global__ __launch_bounds__(256) void proj_tc_kernel(const float* __restrict__ xtr,
                                                      const float* __restrict__ xt) {
    // Xh 16K | Xl 16K | A buf0 (Ah8K+Al8K) | A buf1 (Ah8K+Al8K)
    __shared__ __align__(1024) char psm[65536];
    const uint32_t sb = smem_u32(psm);

    const bool isQ = (blockIdx.x >= 64);
    const float* __restrict__ X = isQ ? xt : xtr;
    float* C = isQ ? g_Q : g_K;
    const int mbase = (blockIdx.x & 63) * 128;

    const int tid = threadIdx.x;
    const int wid = tid >> 5;
    const int lane = tid & 31;
    const int l7 = lane & 7, l15 = lane & 15;
    const int g = lane >> 2, t = lane & 3;
    const int ab = lane >> 3;
    const int arow = l7 + ((ab & 1) << 3);
    const int acs = ab >> 1;
    const int nn_inc = (lane >> 4) & 1;
    const int wr = wid * 16;

    // per-thread X slice: 4 chunks of 8 floats (row c0+row_i, chunk dc_i)
    const int xrow = tid >> 1;             // 0..127 (each thread: 1 row, 4 chunks)
    const int xc0 = (tid & 1) * 4;         // chunks 0-3 or 4-7
    const float* xsrc = X + (size_t)(mbase + xrow) * DIN + xc0 * 8;

    float4 xv[4][2];
#pragma unroll
    for (int c = 0; c < 4; ++c) {
        xv[c][0] = *(const float4*)(xsrc + c * 8);
        xv[c][1] = *(const float4*)(xsrc + c * 8 + 4);
    }

    // A tile 0 -> buf0
    {
        const uint32_t abuf = sb + 32768;
        for (int c = tid; c < 512; c += 256) {
            const int k = c >> 3, dc = c & 7;
            const uint32_t swo = (uint32_t)(k * 128 + ((dc ^ (k & 7)) << 4));
            cp16(abuf + swo, g_Ah + (size_t)k * LD + dc * 8);
            cp16(abuf + 8192 + swo, g_Al + (size_t)k * LD + dc * 8);
        }
        CP_COMMIT;
    }

    float oacc[8][4];
#pragma unroll
    for (int n = 0; n < 8; ++n)
#pragma unroll
        for (int j = 0; j < 4; ++j) oacc[n][j] = 0.0f;

    for (int kt = 0; kt < 16; ++kt) {
        const uint32_t abuf = sb + 32768 + (uint32_t)(kt & 1) * 16384;

        // split X regs -> smem (prev compute finished at last sync)
#pragma unroll
        for (int c = 0; c < 4; ++c) {
            const int dc = xc0 + c;
            float r0, r1, r2, r3, r4, r5, r6, r7;
            const float h0 = bf_hi_res(xv[c][0].x, r0), h1 = bf_hi_res(xv[c][0].y, r1);
            const float h2 = bf_hi_res(xv[c][0].z, r2), h3 = bf_hi_res(xv[c][0].w, r3);
            const float h4 = bf_hi_res(xv[c][1].x, r4), h5 = bf_hi_res(xv[c][1].y, r5);
            const float h6 = bf_hi_res(xv[c][1].z, r6), h7 = bf_hi_res(xv[c][1].w, r7);
            uint4 ph, pl;
            ph.x = pack_bf16(h0, h1); ph.y = pack_bf16(h2, h3);
            ph.z = pack_bf16(h4, h5); ph.w = pack_bf16(h6, h7);
            pl.x = pack_bf16(r0, r1); pl.y = pack_bf16(r2, r3);
            pl.z = pack_bf16(r4, r5); pl.w = pack_bf16(r6, r7);
            const uint32_t swo = (uint32_t)(xrow * 128 + ((dc ^ (xrow & 7)) << 4));
            *(uint4*)(psm + swo) = ph;
            *(uint4*)(psm + 16384 + swo) = pl;
        }

        // prefetch next A tile + next X registers
        if (kt + 1 < 16) {
            const uint32_t anext = sb + 32768 + (uint32_t)((kt + 1) & 1) * 16384;
            const int k0n = (kt + 1) * 64;
            for (int c = tid; c < 512; c += 256) {
                const int k = c >> 3, dc = c & 7;
                const uint32_t swo = (uint32_t)(k * 128 + ((dc ^ (k & 7)) << 4));
                cp16(anext + swo, g_Ah + (size_t)(k0n + k) * LD + dc * 8);
                cp16(anext + 8192 + swo, g_Al + (size_t)(k0n + k) * LD + dc * 8);
            }
            CP_COMMIT;
#pragma unroll
            for (int c = 0; c < 4; ++c) {
                xv[c][0] = *(const float4*)(xsrc + k0n + c * 8);
                xv[c][1] = *(const float4*)(xsrc + k0n + c * 8 + 4);
            }
            CP_WAIT1;  // current A tile done; next still in flight
        } else {
            CP_WAIT0;
        }
        __syncthreads();

        const uint32_t xa_base = sb + (uint32_t)((wr + arow) * 128);
#pragma unroll
        for (int ks = 0; ks < 4; ++ks) {
            uint32_t axh[4], axl[4];
            const uint32_t qaddr = xa_base + (uint32_t)((((ks << 1) + acs) ^ l7) << 4);
            ldsm_x4(axh, qaddr);
            ldsm_x4(axl, qaddr + 16384);
            const uint32_t brow = abuf + (uint32_t)((ks * 16 + l15) * 128);
#pragma unroll
            for (int n = 0; n < 8; n += 2) {
                const uint32_t baddr = brow + (uint32_t)(((n + nn_inc) ^ l7) << 4);
                uint32_t bh[4], bl[4];
                ldsm_x4t(bh, baddr);
                ldsm_x4t(bl, baddr + 8192);
                mma_bf16(oacc[n], axh, bh[0], bh[1]);
                mma_bf16(oacc[n], axl, bh[0], bh[1]);
                mma_bf16(oacc[n], axh, bl[0], bl[1]);
                mma_bf16(oacc[n + 1], axh, bh[2], bh[3]);
                mma_bf16(oacc[n + 1], axl, bh[2], bh[3]);
                mma_bf16(oacc[n + 1], axh, bl[2], bl[3]);
            }
        }
        __syncthreads();
    }

    const int row0 = mbase + wr + g;
#pragma unroll
    for (int n = 0; n < 8; ++n) {
        *(float2*)(C + (size_t)row0 * LD + n * 8 + 2 * t) =
            make_float2(oacc[n][0], oacc[n][1]);
        *(float2*)(C + (size_t)(row0 + 8) * LD + n * 8 + 2 * t) =
            make_float2(oacc[n][2], oacc[n][3]);
    }
}

// ---------------------------------------------------------------------------
__global__ __launch_bounds__(256) void colmean_kernel() {
    __shared__ float red[256];
    const int l = blockIdx.x;
    float s = 0.0f;
    for (int r = threadIdx.x; r < NTR; r += 256) s += g_K[(size_t)r * LD + l];
    red[threadIdx.x] = s;
    __syncthreads();
    for (int off = 128; off > 0; off >>= 1) {
        if (threadIdx.x < off) red[threadIdx.x] += red[threadIdx.x + off];
        __syncthreads();
    }
    if (threadIdx.x == 0) g_muA[l] = red[0] * (1.0f / (float)NTR);
}

// ---------------------------------------------------------------------------
// center + bf16 split of Q/K
// ---------------------------------------------------------------------------
__global__ __launch_bounds__(256) void split_qk_kernel() {
    int i = blockIdx.x * 256 + threadIdx.x;      // 0..262143 float4 elems
    const bool isQ = (i >= 131072);
    const float* src = isQ ? g_Q : g_K;
    __nv_bfloat16* dh = isQ ? g_Qh : g_Kh;
    __nv_bfloat16* dl = isQ ? g_Ql : g_Kl;
    const int j = isQ ? i - 131072 : i;
    float4 v = ((const float4*)src)[j];
    const int l = (j * 4) & 63;
    v.x -= g_muA[l + 0];
    v.y -= g_muA[l + 1];
    v.z -= g_muA[l + 2];
    v.w -= g_muA[l + 3];
    float r0, r1, r2, r3;
    const float h0 = bf_hi_res(v.x, r0), h1 = bf_hi_res(v.y, r1);
    const float h2 = bf_hi_res(v.z, r2), h3 = bf_hi_res(v.w, r3);
    uint2 ph, pl;
    ph.x = pack_bf16(h0, h1); ph.y = pack_bf16(h2, h3);
    pl.x = pack_bf16(r0, r1); pl.y = pack_bf16(r2, r3);
    ((uint2*)dh)[j] = ph;
    ((uint2*)dl)[j] = pl;
}

// ---------------------------------------------------------------------------
// V split (keeps [key][dy] layout): ytr [8192,128] f32 -> Vh/Vl bf16
// ---------------------------------------------------------------------------
__global__ __launch_bounds__(256) void vsplit_kernel(const float* __restrict__ ytr) {
    const int i = blockIdx.x * 256 + threadIdx.x;  // float4 idx, 262144 total
    float4 v = ((const float4*)ytr)[i];
    float r0, r1, r2, r3;
    const float h0 = bf_hi_res(v.x, r0), h1 = bf_hi_res(v.y, r1);
    const float h2 = bf_hi_res(v.z, r2), h3 = bf_hi_res(v.w, r3);
    uint2 ph, pl;
    ph.x = pack_bf16(h0, h1); ph.y = pack_bf16(h2, h3);
    pl.x = pack_bf16(r0, r1); pl.y = pack_bf16(r2, r3);
    ((uint2*)g_Vh)[i] = ph;
    ((uint2*)g_Vl)[i] = pl;
}

// ---------------------------------------------------------------------------
// flash kernel — EXACT round-4 structure (294us config): single buffer,
// x2 ldmatrix, immediate cp.async wait.
// ---------------------------------------------------------------------------
#define FB_QH 0
#define FB_QL 16384
#define FB_KH 32768
#define FB_KL 49152
#define FB_VH 65536
#define FB_VL 98304
#define FSM_BYTES 131072

extern __shared__ char fsm[];

__global__ __launch_bounds__(256) void flash_mma_kernel() {
    const int tid = threadIdx.x;
    const int wid = tid >> 5;
    const int lane = tid & 31;
    const int g = lane >> 2;
    const int t = lane & 3;
    const int qblk = blockIdx.x >> 1;
    const int half = blockIdx.x & 1;
    const int qbase = qblk * 128;
    const int wr = wid * 16;
    const uint32_t sb = smem_u32(fsm);

    for (int c = tid; c < 1024; c += 256) {
        const int row = c >> 3, dc = c & 7;
        const uint32_t dst = sb + FB_QH + row * 128 + ((dc ^ (row & 7)) << 4);
        const size_t gq = ((size_t)(qbase + row) << 6) + dc * 8;
        cp16(dst, g_Qh + gq);
        cp16(dst + (FB_QL - FB_QH), g_Ql + gq);
    }
    CP_COMMIT;

    const int l7 = lane & 7, l15 = lane & 15;
    const int ab = lane >> 3;
    const int arow = l7 + ((ab & 1) << 3);
    const int acs = ab >> 1;
    const int kcb = (lane >> 3) & 1;
    const uint32_t qa_base = sb + FB_QH + (uint32_t)(wr + arow) * 128;
    const uint32_t va_base = sb + FB_VH + (uint32_t)l15 * 256;

    float oacc[16][4];
#pragma unroll
    for (int n = 0; n < 16; ++n)
#pragma unroll
        for (int j = 0; j < 4; ++j) oacc[n][j] = 0.0f;
    float rlo = 0.0f, rhi = 0.0f;

    CP_WAIT0;
    __syncthreads();

    for (int jt = 0; jt < 32; ++jt) {
        const int kb = (half * 32 + jt) * 128;

        for (int c = tid; c < 1024; c += 256) {
            const int key = c >> 3, dc = c & 7;
            const uint32_t dst = sb + FB_KH + key * 128 + ((dc ^ (key & 7)) << 4);
            const size_t gk = ((size_t)(kb + key) << 6) + dc * 8;
            cp16(dst, g_Kh + gk);
            cp16(dst + (FB_KL - FB_KH), g_Kl + gk);
        }
        for (int c = tid; c < 2048; c += 256) {
            const int key = c >> 4, dc = c & 15;
            const uint32_t dst = sb + FB_VH + key * 256 + ((dc ^ (key & 7)) << 4);
            const size_t gv = ((size_t)(kb + key) << 7) + dc * 8;
            cp16(dst, g_Vh + gv);
            cp16(dst + (FB_VL - FB_VH), g_Vl + gv);
        }
        CP_COMMIT;
        CP_WAIT0;
        __syncthreads();

        float sacc[16][4];
#pragma unroll
        for (int n = 0; n < 16; ++n)
#pragma unroll
            for (int j = 0; j < 4; ++j) sacc[n][j] = 0.0f;

#pragma unroll
        for (int ks = 0; ks < 4; ++ks) {
            uint32_t aqh[4], aql[4];
            const uint32_t qaddr =
                qa_base + (uint32_t)((((ks << 1) + acs) ^ l7) << 4);
            ldsm_x4(aqh, qaddr);
            ldsm_x4(aql, qaddr + (FB_QL - FB_QH));
            const uint32_t ksw = (uint32_t)((((ks << 1) + kcb) ^ l7) << 4);
#pragma unroll
            for (int n = 0; n < 16; ++n) {
                const uint32_t kaddr =
                    sb + FB_KH + (uint32_t)(((n << 3) + l7) * 128) + ksw;
                uint32_t bh0, bh1, bl0, bl1;
                ldsm_x2(bh0, bh1, kaddr);
                ldsm_x2(bl0, bl1, kaddr + (FB_KL - FB_KH));
                mma_bf16(sacc[n], aqh, bh0, bh1);
                mma_bf16(sacc[n], aql, bh0, bh1);
                mma_bf16(sacc[n], aqh, bl0, bl1);
            }
        }

        uint32_t ph[16][2], pl[16][2];
#pragma unroll
        for (int n = 0; n < 16; ++n) {
            const float e0 = __expf(sacc[n][0]);
            const float e1 = __expf(sacc[n][1]);
            const float e2 = __expf(sacc[n][2]);
            const float e3 = __expf(sacc[n][3]);
            rlo += e0 + e1;
            rhi += e2 + e3;
            float r0, r1, r2, r3;
            const float h0 = bf_hi_res(e0, r0), h1 = bf_hi_res(e1, r1);
            const float h2 = bf_hi_res(e2, r2), h3 = bf_hi_res(e3, r3);
            ph[n][0] = pack_bf16(h0, h1);
            ph[n][1] = pack_bf16(h2, h3);
            pl[n][0] = pack_bf16(r0, r1);
            pl[n][1] = pack_bf16(r2, r3);
        }

#pragma unroll
        for (int s = 0; s < 8; ++s) {
            const uint32_t ah[4] = {ph[2 * s][0], ph[2 * s][1],
                                    ph[2 * s + 1][0], ph[2 * s + 1][1]};
            const uint32_t al[4] = {pl[2 * s][0], pl[2 * s][1],
                                    pl[2 * s + 1][0], pl[2 * s + 1][1]};
            const uint32_t vsb = va_base + (uint32_t)(s << 12);
#pragma unroll
            for (int n = 0; n < 16; ++n) {
                const uint32_t vaddr = vsb + (uint32_t)((n ^ l7) << 4);
                uint32_t vh0, vh1, vl0, vl1;
                ldsm_x2t(vh0, vh1, vaddr);
                ldsm_x2t(vl0, vl1, vaddr + (FB_VL - FB_VH));
                mma_bf16(oacc[n], ah, vh0, vh1);
                mma_bf16(oacc[n], al, vh0, vh1);
                mma_bf16(oacc[n], ah, vl0, vl1);
            }
        }
        __syncthreads();
    }

    float* Op = g_Opart + (size_t)half * NT * DY;
    const int row0 = qbase + wr + g;
#pragma unroll
    for (int n = 0; n < 16; ++n) {
        *(float2*)(Op + (size_t)row0 * DY + n * 8 + 2 * t) =
            make_float2(oacc[n][0], oacc[n][1]);
        *(float2*)(Op + (size_t)(row0 + 8) * DY + n * 8 + 2 * t) =
            make_float2(oacc[n][2], oacc[n][3]);
    }
    rlo += __shfl_xor_sync(0xffffffffu, rlo, 1);
    rlo += __shfl_xor_sync(0xffffffffu, rlo, 2);
    rhi += __shfl_xor_sync(0xffffffffu, rhi, 1);
    rhi += __shfl_xor_sync(0xffffffffu, rhi, 2);
    if (t == 0) {
        g_lpart[(size_t)half * NT + row0] = rlo;
        g_lpart[(size_t)half * NT + row0 + 8] = rhi;
    }
}

// ---------------------------------------------------------------------------
// combine: out = (O0 + O1) / (l0 + l1)
// ---------------------------------------------------------------------------
__global__ __launch_bounds__(256) void combine_kernel(float* __restrict__ out) {
    const int i = blockIdx.x * 256 + threadIdx.x;  // float4 index, 262144 total
    const int r = (i * 4) >> 7;                    // query row
    const float inv = 1.0f / (g_lpart[r] + g_lpart[NT + r]);
    float4 a = ((const float4*)g_Opart)[i];
    float4 b = ((const float4*)(g_Opart + (size_t)NT * DY))[i];
    ((float4*)out)[i] = make_float4((a.x + b.x) * inv, (a.y + b.y) * inv,
                                    (a.z + b.z) * inv, (a.w + b.w) * inv);
}

// ---------------------------------------------------------------------------
extern "C" void kernel_launch(void* const* d_in, const int* in_sizes, int n_in,
                              void* d_out, int out_size) {
    const float* xtr = (const float*)d_in[0];
    const float* ytr = (const float*)d_in[1];
    const float* xt  = (const float*)d_in[2];
    const float* A   = (const float*)d_in[3];
    float* out = (float*)d_out;

    cudaFuncSetAttribute(flash_mma_kernel,
                         cudaFuncAttributeMaxDynamicSharedMemorySize, FSM_BYTES);

    asplit_kernel<<<64, 256>>>(A);
    proj_tc_kernel<<<128, 256>>>(xtr, xt);
    colmean_kernel<<<64, 256>>>();
    split_qk_kernel<<<1024, 256>>>();
    vsplit_kernel<<<1024, 256>>>(ytr);
    flash_mma_kernel<<<128, 256, FSM_BYTES>>>();
    combine_kernel<<<1024, 256>>>(out);
}

// round 9
// speedup vs baseline: 1.1935x; 1.0159x over previous
#include <cuda_runtime.h>
#include <cuda_bf16.h>
#include <cstdint>

#define NTR 8192
#define NT  8192
#define DIN 1024
#define LD  64
#define DY  128

// ---------------------------------------------------------------------------
// device scratch (no allocations allowed)
// ---------------------------------------------------------------------------
__device__ float g_Q[(size_t)NT * LD];
__device__ float g_K[(size_t)NTR * LD];
__device__ float g_muA[LD];
__device__ __nv_bfloat16 g_Ah[(size_t)DIN * LD];
__device__ __nv_bfloat16 g_Al[(size_t)DIN * LD];
__device__ __nv_bfloat16 g_Qh[(size_t)NT * LD];
__device__ __nv_bfloat16 g_Ql[(size_t)NT * LD];
__device__ __nv_bfloat16 g_Kh[(size_t)NTR * LD];
__device__ __nv_bfloat16 g_Kl[(size_t)NTR * LD];
__device__ __nv_bfloat16 g_Vh[(size_t)NTR * DY];
__device__ __nv_bfloat16 g_Vl[(size_t)NTR * DY];
__device__ float g_Opart[2 * (size_t)NT * DY];
__device__ float g_lpart[2 * (size_t)NT];

// ---------------------------------------------------------------------------
// helpers (portable PTX only: sm_80-level mma/ldmatrix/cp.async)
// ---------------------------------------------------------------------------
__device__ __forceinline__ uint32_t smem_u32(const void* p) {
    uint32_t a;
    asm("{ .reg .u64 t; cvta.to.shared.u64 t, %1; cvt.u32.u64 %0, t; }"
        : "=r"(a) : "l"(p));
    return a;
}

__device__ __forceinline__ void cp16(uint32_t dst, const void* src) {
    asm volatile("cp.async.cg.shared.global [%0], [%1], 16;"
                 :: "r"(dst), "l"(src));
}
#define CP_COMMIT asm volatile("cp.async.commit_group;" ::: "memory")
#define CP_WAIT0  asm volatile("cp.async.wait_group 0;" ::: "memory")
#define CP_WAIT1  asm volatile("cp.async.wait_group 1;" ::: "memory")

__device__ __forceinline__ void ldsm_x4(uint32_t* r, uint32_t a) {
    asm volatile("ldmatrix.sync.aligned.m8n8.x4.shared.b16 {%0,%1,%2,%3}, [%4];"
                 : "=r"(r[0]), "=r"(r[1]), "=r"(r[2]), "=r"(r[3]) : "r"(a));
}
__device__ __forceinline__ void ldsm_x2(uint32_t& r0, uint32_t& r1, uint32_t a) {
    asm volatile("ldmatrix.sync.aligned.m8n8.x2.shared.b16 {%0,%1}, [%2];"
                 : "=r"(r0), "=r"(r1) : "r"(a));
}
__device__ __forceinline__ void ldsm_x2t(uint32_t& r0, uint32_t& r1, uint32_t a) {
    asm volatile("ldmatrix.sync.aligned.m8n8.x2.trans.shared.b16 {%0,%1}, [%2];"
                 : "=r"(r0), "=r"(r1) : "r"(a));
}
__device__ __forceinline__ void ldsm_x4t(uint32_t* r, uint32_t a) {
    asm volatile("ldmatrix.sync.aligned.m8n8.x4.trans.shared.b16 {%0,%1,%2,%3}, [%4];"
                 : "=r"(r[0]), "=r"(r[1]), "=r"(r[2]), "=r"(r[3]) : "r"(a));
}
__device__ __forceinline__ void mma_bf16(float* c, const uint32_t* a,
                                         uint32_t b0, uint32_t b1) {
    asm volatile(
        "mma.sync.aligned.m16n8k16.row.col.f32.bf16.bf16.f32 "
        "{%0,%1,%2,%3}, {%4,%5,%6,%7}, {%8,%9}, {%0,%1,%2,%3};"
        : "+f"(c[0]), "+f"(c[1]), "+f"(c[2]), "+f"(c[3])
        : "r"(a[0]), "r"(a[1]), "r"(a[2]), "r"(a[3]), "r"(b0), "r"(b1));
}

__device__ __forceinline__ uint32_t pack_bf16(float a, float b) {
    const unsigned short ha = __bfloat16_as_ushort(__float2bfloat16(a));
    const unsigned short hb = __bfloat16_as_ushort(__float2bfloat16(b));
    return (uint32_t)ha | ((uint32_t)hb << 16);
}
__device__ __forceinline__ float bf_hi_res(float v, float& res) {
    const __nv_bfloat16 h = __float2bfloat16(v);
    res = v - __bfloat162float(h);
    return __bfloat162float(h);
}

// ---------------------------------------------------------------------------
// A split: A[1024,64] f32 -> g_Ah/g_Al bf16
// ---------------------------------------------------------------------------
__global__ __launch_bounds__(256) void asplit_kernel(const float* __restrict__ A) {
    const int i = blockIdx.x * 256 + threadIdx.x;  // float4 idx, 16384 total
    float4 v = ((const float4*)A)[i];
    float r0, r1, r2, r3;
    const float h0 = bf_hi_res(v.x, r0), h1 = bf_hi_res(v.y, r1);
    const float h2 = bf_hi_res(v.z, r2), h3 = bf_hi_res(v.w, r3);
    uint2 ph, pl;
    ph.x = pack_bf16(h0, h1); ph.y = pack_bf16(h2, h3);
    pl.x = pack_bf16(r0, r1); pl.y = pack_bf16(r2, r3);
    ((uint2*)g_Ah)[i] = ph;
    ((uint2*)g_Al)[i] = pl;
}

// ---------------------------------------------------------------------------
// Tensor-core projection, pipelined (unchanged from round 8)
// ---------------------------------------------------------------------------
__global__ __launch_bounds__(256) void proj_tc_kernel(const float* __restrict__ xtr,
                                                      const float* __restrict__ xt) {
    __shared__ __align__(1024) char psm[65536];
    const uint32_t sb = smem_u32(psm);

    const bool isQ = (blockIdx.x >= 64);
    const float* __restrict__ X = isQ ? xt : xtr;
    float* C = isQ ? g_Q : g_K;
    const int mbase = (blockIdx.x & 63) * 128;

    const int tid = threadIdx.x;
    const int wid = tid >> 5;
    const int lane = tid & 31;
    const int l7 = lane & 7, l15 = lane & 15;
    const int g = lane >> 2, t = lane & 3;
    const int ab = lane >> 3;
    const int arow = l7 + ((ab & 1) << 3);
    const int acs = ab >> 1;
    const int nn_inc = (lane >> 4) & 1;
    const int wr = wid * 16;

    const int xrow = tid >> 1;
    const int xc0 = (tid & 1) * 4;
    const float* xsrc = X + (size_t)(mbase + xrow) * DIN + xc0 * 8;

    float4 xv[4][2];
#pragma unroll
    for (int c = 0; c < 4; ++c) {
        xv[c][0] = *(const float4*)(xsrc + c * 8);
        xv[c][1] = *(const float4*)(xsrc + c * 8 + 4);
    }

    {
        const uint32_t abuf = sb + 32768;
        for (int c = tid; c < 512; c += 256) {
            const int k = c >> 3, dc = c & 7;
            const uint32_t swo = (uint32_t)(k * 128 + ((dc ^ (k & 7)) << 4));
            cp16(abuf + swo, g_Ah + (size_t)k * LD + dc * 8);
            cp16(abuf + 8192 + swo, g_Al + (size_t)k * LD + dc * 8);
        }
        CP_COMMIT;
    }

    float oacc[8][4];
#pragma unroll
    for (int n = 0; n < 8; ++n)
#pragma unroll
        for (int j = 0; j < 4; ++j) oacc[n][j] = 0.0f;

    for (int kt = 0; kt < 16; ++kt) {
        const uint32_t abuf = sb + 32768 + (uint32_t)(kt & 1) * 16384;

#pragma unroll
        for (int c = 0; c < 4; ++c) {
            const int dc = xc0 + c;
            float r0, r1, r2, r3, r4, r5, r6, r7;
            const float h0 = bf_hi_res(xv[c][0].x, r0), h1 = bf_hi_res(xv[c][0].y, r1);
            const float h2 = bf_hi_res(xv[c][0].z, r2), h3 = bf_hi_res(xv[c][0].w, r3);
            const float h4 = bf_hi_res(xv[c][1].x, r4), h5 = bf_hi_res(xv[c][1].y, r5);
            const float h6 = bf_hi_res(xv[c][1].z, r6), h7 = bf_hi_res(xv[c][1].w, r7);
            uint4 ph, pl;
            ph.x = pack_bf16(h0, h1); ph.y = pack_bf16(h2, h3);
            ph.z = pack_bf16(h4, h5); ph.w = pack_bf16(h6, h7);
            pl.x = pack_bf16(r0, r1); pl.y = pack_bf16(r2, r3);
            pl.z = pack_bf16(r4, r5); pl.w = pack_bf16(r6, r7);
            const uint32_t swo = (uint32_t)(xrow * 128 + ((dc ^ (xrow & 7)) << 4));
            *(uint4*)(psm + swo) = ph;
            *(uint4*)(psm + 16384 + swo) = pl;
        }

        if (kt + 1 < 16) {
            const uint32_t anext = sb + 32768 + (uint32_t)((kt + 1) & 1) * 16384;
            const int k0n = (kt + 1) * 64;
            for (int c = tid; c < 512; c += 256) {
                const int k = c >> 3, dc = c & 7;
                const uint32_t swo = (uint32_t)(k * 128 + ((dc ^ (k & 7)) << 4));
                cp16(anext + swo, g_Ah + (size_t)(k0n + k) * LD + dc * 8);
                cp16(anext + 8192 + swo, g_Al + (size_t)(k0n + k) * LD + dc * 8);
            }
            CP_COMMIT;
#pragma unroll
            for (int c = 0; c < 4; ++c) {
                xv[c][0] = *(const float4*)(xsrc + k0n + c * 8);
                xv[c][1] = *(const float4*)(xsrc + k0n + c * 8 + 4);
            }
            CP_WAIT1;
        } else {
            CP_WAIT0;
        }
        __syncthreads();

        const uint32_t xa_base = sb + (uint32_t)((wr + arow) * 128);
#pragma unroll
        for (int ks = 0; ks < 4; ++ks) {
            uint32_t axh[4], axl[4];
            const uint32_t qaddr = xa_base + (uint32_t)((((ks << 1) + acs) ^ l7) << 4);
            ldsm_x4(axh, qaddr);
            ldsm_x4(axl, qaddr + 16384);
            const uint32_t brow = abuf + (uint32_t)((ks * 16 + l15) * 128);
#pragma unroll
            for (int n = 0; n < 8; n += 2) {
                const uint32_t baddr = brow + (uint32_t)(((n + nn_inc) ^ l7) << 4);
                uint32_t bh[4], bl[4];
                ldsm_x4t(bh, baddr);
                ldsm_x4t(bl, baddr + 8192);
                mma_bf16(oacc[n], axh, bh[0], bh[1]);
                mma_bf16(oacc[n], axl, bh[0], bh[1]);
                mma_bf16(oacc[n], axh, bl[0], bl[1]);
                mma_bf16(oacc[n + 1], axh, bh[2], bh[3]);
                mma_bf16(oacc[n + 1], axl, bh[2], bh[3]);
                mma_bf16(oacc[n + 1], axh, bl[2], bl[3]);
            }
        }
        __syncthreads();
    }

    const int row0 = mbase + wr + g;
#pragma unroll
    for (int n = 0; n < 8; ++n) {
        *(float2*)(C + (size_t)row0 * LD + n * 8 + 2 * t) =
            make_float2(oacc[n][0], oacc[n][1]);
        *(float2*)(C + (size_t)(row0 + 8) * LD + n * 8 + 2 * t) =
            make_float2(oacc[n][2], oacc[n][3]);
    }
}

// ---------------------------------------------------------------------------
__global__ __launch_bounds__(256) void colmean_kernel() {
    __shared__ float red[256];
    const int l = blockIdx.x;
    float s = 0.0f;
    for (int r = threadIdx.x; r < NTR; r += 256) s += g_K[(size_t)r * LD + l];
    red[threadIdx.x] = s;
    __syncthreads();
    for (int off = 128; off > 0; off >>= 1) {
        if (threadIdx.x < off) red[threadIdx.x] += red[threadIdx.x + off];
        __syncthreads();
    }
    if (threadIdx.x == 0) g_muA[l] = red[0] * (1.0f / (float)NTR);
}

// ---------------------------------------------------------------------------
// center + bf16 split of Q/K
// ---------------------------------------------------------------------------
__global__ __launch_bounds__(256) void split_qk_kernel() {
    int i = blockIdx.x * 256 + threadIdx.x;
    const bool isQ = (i >= 131072);
    const float* src = isQ ? g_Q : g_K;
    __nv_bfloat16* dh = isQ ? g_Qh : g_Kh;
    __nv_bfloat16* dl = isQ ? g_Ql : g_Kl;
    const int j = isQ ? i - 131072 : i;
    float4 v = ((const float4*)src)[j];
    const int l = (j * 4) & 63;
    v.x -= g_muA[l + 0];
    v.y -= g_muA[l + 1];
    v.z -= g_muA[l + 2];
    v.w -= g_muA[l + 3];
    float r0, r1, r2, r3;
    const float h0 = bf_hi_res(v.x, r0), h1 = bf_hi_res(v.y, r1);
    const float h2 = bf_hi_res(v.z, r2), h3 = bf_hi_res(v.w, r3);
    uint2 ph, pl;
    ph.x = pack_bf16(h0, h1); ph.y = pack_bf16(h2, h3);
    pl.x = pack_bf16(r0, r1); pl.y = pack_bf16(r2, r3);
    ((uint2*)dh)[j] = ph;
    ((uint2*)dl)[j] = pl;
}

// ---------------------------------------------------------------------------
// V split (keeps [key][dy] layout): ytr [8192,128] f32 -> Vh/Vl bf16
// ---------------------------------------------------------------------------
__global__ __launch_bounds__(256) void vsplit_kernel(const float* __restrict__ ytr) {
    const int i = blockIdx.x * 256 + threadIdx.x;
    float4 v = ((const float4*)ytr)[i];
    float r0, r1, r2, r3;
    const float h0 = bf_hi_res(v.x, r0), h1 = bf_hi_res(v.y, r1);
    const float h2 = bf_hi_res(v.z, r2), h3 = bf_hi_res(v.w, r3);
    uint2 ph, pl;
    ph.x = pack_bf16(h0, h1); ph.y = pack_bf16(h2, h3);
    pl.x = pack_bf16(r0, r1); pl.y = pack_bf16(r2, r3);
    ((uint2*)g_Vh)[i] = ph;
    ((uint2*)g_Vl)[i] = pl;
}

// ---------------------------------------------------------------------------
// flash kernel — round-4 compute structure, with K double-buffered (2x32KB)
// and V single-buffered (64KB). V load overlaps QK compute; next-K load
// overlaps PV compute. smem total 160KB.
// ---------------------------------------------------------------------------
#define FB_QH 0
#define FB_QL 16384
#define FB_KB 32768
// K buf b at FB_KB + b*32768: KH +0, KL +16384
#define FB_VH 98304
#define FB_VL 131072
#define FSM_BYTES 163840

extern __shared__ char fsm[];

__device__ __forceinline__ void load_K_tile(uint32_t sb, int buf, int kb, int tid) {
    const uint32_t base = sb + FB_KB + (uint32_t)buf * 32768;
    for (int c = tid; c < 1024; c += 256) {
        const int key = c >> 3, dc = c & 7;
        const uint32_t dst = base + key * 128 + ((dc ^ (key & 7)) << 4);
        const size_t gk = ((size_t)(kb + key) << 6) + dc * 8;
        cp16(dst, g_Kh + gk);
        cp16(dst + 16384, g_Kl + gk);
    }
}

__global__ __launch_bounds__(256) void flash_mma_kernel() {
    const int tid = threadIdx.x;
    const int wid = tid >> 5;
    const int lane = tid & 31;
    const int g = lane >> 2;
    const int t = lane & 3;
    const int qblk = blockIdx.x >> 1;
    const int half = blockIdx.x & 1;
    const int qbase = qblk * 128;
    const int wr = wid * 16;
    const uint32_t sb = smem_u32(fsm);

    // ---- prologue: Q tile + K tile 0 in one cp group
    for (int c = tid; c < 1024; c += 256) {
        const int row = c >> 3, dc = c & 7;
        const uint32_t dst = sb + FB_QH + row * 128 + ((dc ^ (row & 7)) << 4);
        const size_t gq = ((size_t)(qbase + row) << 6) + dc * 8;
        cp16(dst, g_Qh + gq);
        cp16(dst + (FB_QL - FB_QH), g_Ql + gq);
    }
    load_K_tile(sb, 0, half * 4096, tid);
    CP_COMMIT;

    const int l7 = lane & 7, l15 = lane & 15;
    const int ab = lane >> 3;
    const int arow = l7 + ((ab & 1) << 3);
    const int acs = ab >> 1;
    const int kcb = (lane >> 3) & 1;
    const uint32_t qa_base = sb + FB_QH + (uint32_t)(wr + arow) * 128;
    const uint32_t va_base = sb + FB_VH + (uint32_t)l15 * 256;

    float oacc[16][4];
#pragma unroll
    for (int n = 0; n < 16; ++n)
#pragma unroll
        for (int j = 0; j < 4; ++j) oacc[n][j] = 0.0f;
    float rlo = 0.0f, rhi = 0.0f;

    for (int jt = 0; jt < 32; ++jt) {
        const int kb = (half * 32 + jt) * 128;
        const uint32_t kbase = sb + FB_KB + (uint32_t)(jt & 1) * 32768;

        CP_WAIT0;          // K(jt) (and Q on first iter) resident
        __syncthreads();   // also guards V buffer: all PV(jt-1) reads done

        // ---- V(jt) load, overlapped with QK compute
        for (int c = tid; c < 2048; c += 256) {
            const int key = c >> 4, dc = c & 15;
            const uint32_t dst = sb + FB_VH + key * 256 + ((dc ^ (key & 7)) << 4);
            const size_t gv = ((size_t)(kb + key) << 7) + dc * 8;
            cp16(dst, g_Vh + gv);
            cp16(dst + (FB_VL - FB_VH), g_Vl + gv);
        }
        CP_COMMIT;

        // ---- S = Q K^T
        float sacc[16][4];
#pragma unroll
        for (int n = 0; n < 16; ++n)
#pragma unroll
            for (int j = 0; j < 4; ++j) sacc[n][j] = 0.0f;

#pragma unroll
        for (int ks = 0; ks < 4; ++ks) {
            uint32_t aqh[4], aql[4];
            const uint32_t qaddr =
                qa_base + (uint32_t)((((ks << 1) + acs) ^ l7) << 4);
            ldsm_x4(aqh, qaddr);
            ldsm_x4(aql, qaddr + (FB_QL - FB_QH));
            const uint32_t ksw = (uint32_t)((((ks << 1) + kcb) ^ l7) << 4);
#pragma unroll
            for (int n = 0; n < 16; ++n) {
                const uint32_t kaddr =
                    kbase + (uint32_t)(((n << 3) + l7) * 128) + ksw;
                uint32_t bh0, bh1, bl0, bl1;
                ldsm_x2(bh0, bh1, kaddr);
                ldsm_x2(bl0, bl1, kaddr + 16384);
                mma_bf16(sacc[n], aqh, bh0, bh1);
                mma_bf16(sacc[n], aql, bh0, bh1);
                mma_bf16(sacc[n], aqh, bl0, bl1);
            }
        }

        // ---- prefetch K(jt+1) into the other buffer (overlaps exp+PV)
        if (jt + 1 < 32) {
            load_K_tile(sb, (jt + 1) & 1, kb + 128, tid);
            CP_COMMIT;
            CP_WAIT1;      // V(jt) done; K(jt+1) still in flight
        } else {
            CP_WAIT0;      // V(jt) done
        }

        // ---- P = exp(S), pack into A-fragments (hi + lo)
        uint32_t ph[16][2], pl[16][2];
#pragma unroll
        for (int n = 0; n < 16; ++n) {
            const float e0 = __expf(sacc[n][0]);
            const float e1 = __expf(sacc[n][1]);
            const float e2 = __expf(sacc[n][2]);
            const float e3 = __expf(sacc[n][3]);
            rlo += e0 + e1;
            rhi += e2 + e3;
            float r0, r1, r2, r3;
            const float h0 = bf_hi_res(e0, r0), h1 = bf_hi_res(e1, r1);
            const float h2 = bf_hi_res(e2, r2), h3 = bf_hi_res(e3, r3);
            ph[n][0] = pack_bf16(h0, h1);
            ph[n][1] = pack_bf16(h2, h3);
            pl[n][0] = pack_bf16(r0, r1);
            pl[n][1] = pack_bf16(r2, r3);
        }
        __syncthreads();   // V writes visible to all warps' ldmatrix

        // ---- O += P V
#pragma unroll
        for (int s = 0; s < 8; ++s) {
            const uint32_t ah[4] = {ph[2 * s][0], ph[2 * s][1],
                                    ph[2 * s + 1][0], ph[2 * s + 1][1]};
            const uint32_t al[4] = {pl[2 * s][0], pl[2 * s][1],
                                    pl[2 * s + 1][0], pl[2 * s + 1][1]};
            const uint32_t vsb = va_base + (uint32_t)(s << 12);
#pragma unroll
            for (int n = 0; n < 16; ++n) {
                const uint32_t vaddr = vsb + (uint32_t)((n ^ l7) << 4);
                uint32_t vh0, vh1, vl0, vl1;
                ldsm_x2t(vh0, vh1, vaddr);
                ldsm_x2t(vl0, vl1, vaddr + (FB_VL - FB_VH));
                mma_bf16(oacc[n], ah, vh0, vh1);
                mma_bf16(oacc[n], al, vh0, vh1);
                mma_bf16(oacc[n], ah, vl0, vl1);
            }
        }
    }

    float* Op = g_Opart + (size_t)half * NT * DY;
    const int row0 = qbase + wr + g;
#pragma unroll
    for (int n = 0; n < 16; ++n) {
        *(float2*)(Op + (size_t)row0 * DY + n * 8 + 2 * t) =
            make_float2(oacc[n][0], oacc[n][1]);
        *(float2*)(Op + (size_t)(row0 + 8) * DY + n * 8 + 2 * t) =
            make_float2(oacc[n][2], oacc[n][3]);
    }
    rlo += __shfl_xor_sync(0xffffffffu, rlo, 1);
    rlo += __shfl_xor_sync(0xffffffffu, rlo, 2);
    rhi += __shfl_xor_sync(0xffffffffu, rhi, 1);
    rhi += __shfl_xor_sync(0xffffffffu, rhi, 2);
    if (t == 0) {
        g_lpart[(size_t)half * NT + row0] = rlo;
        g_lpart[(size_t)half * NT + row0 + 8] = rhi;
    }
}

// ---------------------------------------------------------------------------
// combine: out = (O0 + O1) / (l0 + l1)
// ---------------------------------------------------------------------------
__global__ __launch_bounds__(256) void combine_kernel(float* __restrict__ out) {
    const int i = blockIdx.x * 256 + threadIdx.x;
    const int r = (i * 4) >> 7;
    const float inv = 1.0f / (g_lpart[r] + g_lpart[NT + r]);
    float4 a = ((const float4*)g_Opart)[i];
    float4 b = ((const float4*)(g_Opart + (size_t)NT * DY))[i];
    ((float4*)out)[i] = make_float4((a.x + b.x) * inv, (a.y + b.y) * inv,
                                    (a.z + b.z) * inv, (a.w + b.w) * inv);
}

// ---------------------------------------------------------------------------
extern "C" void kernel_launch(void* const* d_in, const int* in_sizes, int n_in,
                              void* d_out, int out_size) {
    const float* xtr = (const float*)d_in[0];
    const float* ytr = (const float*)d_in[1];
    const float* xt  = (const float*)d_in[2];
    const float* A   = (const float*)d_in[3];
    float* out = (float*)d_out;

    cudaFuncSetAttribute(flash_mma_kernel,
                         cudaFuncAttributeMaxDynamicSharedMemorySize, FSM_BYTES);

    asplit_kernel<<<64, 256>>>(A);
    proj_tc_kernel<<<128, 256>>>(xtr, xt);
    colmean_kernel<<<64, 256>>>();
    split_qk_kernel<<<1024, 256>>>();
    vsplit_kernel<<<1024, 256>>>(ytr);
    flash_mma_kernel<<<128, 256, FSM_BYTES>>>();
    combine_kernel<<<1024, 256>>>(out);
}

// round 10
// speedup vs baseline: 1.2104x; 1.0141x over previous
#include <cuda_runtime.h>
#include <cuda_bf16.h>
#include <cstdint>

#define NTR 8192
#define NT  8192
#define DIN 1024
#define LD  64
#define DY  128

// ---------------------------------------------------------------------------
// device scratch (no allocations allowed)
// ---------------------------------------------------------------------------
__device__ float g_Q[(size_t)NT * LD];
__device__ float g_K[(size_t)NTR * LD];
__device__ float g_muA[LD];
__device__ __nv_bfloat16 g_Ah[(size_t)DIN * LD];
__device__ __nv_bfloat16 g_Al[(size_t)DIN * LD];
__device__ __nv_bfloat16 g_Qh[(size_t)NT * LD];
__device__ __nv_bfloat16 g_Ql[(size_t)NT * LD];
__device__ __nv_bfloat16 g_Kh[(size_t)NTR * LD];
__device__ __nv_bfloat16 g_Kl[(size_t)NTR * LD];
__device__ __nv_bfloat16 g_Vh[(size_t)NTR * DY];
__device__ __nv_bfloat16 g_Vl[(size_t)NTR * DY];
__device__ float g_Opart[2 * (size_t)NT * DY];
__device__ float g_lpart[2 * (size_t)NT];

// ---------------------------------------------------------------------------
// helpers (portable PTX only: sm_80-level mma/ldmatrix/cp.async)
// ---------------------------------------------------------------------------
__device__ __forceinline__ uint32_t smem_u32(const void* p) {
    uint32_t a;
    asm("{ .reg .u64 t; cvta.to.shared.u64 t, %1; cvt.u32.u64 %0, t; }"
        : "=r"(a) : "l"(p));
    return a;
}

__device__ __forceinline__ void cp16(uint32_t dst, const void* src) {
    asm volatile("cp.async.cg.shared.global [%0], [%1], 16;"
                 :: "r"(dst), "l"(src));
}
#define CP_COMMIT asm volatile("cp.async.commit_group;" ::: "memory")
#define CP_WAIT0  asm volatile("cp.async.wait_group 0;" ::: "memory")
#define CP_WAIT1  asm volatile("cp.async.wait_group 1;" ::: "memory")

__device__ __forceinline__ void ldsm_x4(uint32_t* r, uint32_t a) {
    asm volatile("ldmatrix.sync.aligned.m8n8.x4.shared.b16 {%0,%1,%2,%3}, [%4];"
                 : "=r"(r[0]), "=r"(r[1]), "=r"(r[2]), "=r"(r[3]) : "r"(a));
}
__device__ __forceinline__ void ldsm_x4t(uint32_t* r, uint32_t a) {
    asm volatile("ldmatrix.sync.aligned.m8n8.x4.trans.shared.b16 {%0,%1,%2,%3}, [%4];"
                 : "=r"(r[0]), "=r"(r[1]), "=r"(r[2]), "=r"(r[3]) : "r"(a));
}
__device__ __forceinline__ void mma_bf16(float* c, const uint32_t* a,
                                         uint32_t b0, uint32_t b1) {
    asm volatile(
        "mma.sync.aligned.m16n8k16.row.col.f32.bf16.bf16.f32 "
        "{%0,%1,%2,%3}, {%4,%5,%6,%7}, {%8,%9}, {%0,%1,%2,%3};"
        : "+f"(c[0]), "+f"(c[1]), "+f"(c[2]), "+f"(c[3])
        : "r"(a[0]), "r"(a[1]), "r"(a[2]), "r"(a[3]), "r"(b0), "r"(b1));
}

__device__ __forceinline__ uint32_t pack_bf16(float a, float b) {
    const unsigned short ha = __bfloat16_as_ushort(__float2bfloat16(a));
    const unsigned short hb = __bfloat16_as_ushort(__float2bfloat16(b));
    return (uint32_t)ha | ((uint32_t)hb << 16);
}
__device__ __forceinline__ float bf_hi_res(float v, float& res) {
    const __nv_bfloat16 h = __float2bfloat16(v);
    res = v - __bfloat162float(h);
    return __bfloat162float(h);
}

// ---------------------------------------------------------------------------
// A split: A[1024,64] f32 -> g_Ah/g_Al bf16
// ---------------------------------------------------------------------------
__global__ __launch_bounds__(256) void asplit_kernel(const float* __restrict__ A) {
    const int i = blockIdx.x * 256 + threadIdx.x;  // float4 idx, 16384 total
    float4 v = ((const float4*)A)[i];
    float r0, r1, r2, r3;
    const float h0 = bf_hi_res(v.x, r0), h1 = bf_hi_res(v.y, r1);
    const float h2 = bf_hi_res(v.z, r2), h3 = bf_hi_res(v.w, r3);
    uint2 ph, pl;
    ph.x = pack_bf16(h0, h1); ph.y = pack_bf16(h2, h3);
    pl.x = pack_bf16(r0, r1); pl.y = pack_bf16(r2, r3);
    ((uint2*)g_Ah)[i] = ph;
    ((uint2*)g_Al)[i] = pl;
}

// ---------------------------------------------------------------------------
// Tensor-core projection, pipelined (unchanged from round 8/9)
// ---------------------------------------------------------------------------
__global__ __launch_bounds__(256) void proj_tc_kernel(const float* __restrict__ xtr,
                                                      const float* __restrict__ xt) {
    __shared__ __align__(1024) char psm[65536];
    const uint32_t sb = smem_u32(psm);

    const bool isQ = (blockIdx.x >= 64);
    const float* __restrict__ X = isQ ? xt : xtr;
    float* C = isQ ? g_Q : g_K;
    const int mbase = (blockIdx.x & 63) * 128;

    const int tid = threadIdx.x;
    const int wid = tid >> 5;
    const int lane = tid & 31;
    const int l7 = lane & 7, l15 = lane & 15;
    const int g = lane >> 2, t = lane & 3;
    const int ab = lane >> 3;
    const int arow = l7 + ((ab & 1) << 3);
    const int acs = ab >> 1;
    const int nn_inc = (lane >> 4) & 1;
    const int wr = wid * 16;

    const int xrow = tid >> 1;
    const int xc0 = (tid & 1) * 4;
    const float* xsrc = X + (size_t)(mbase + xrow) * DIN + xc0 * 8;

    float4 xv[4][2];
#pragma unroll
    for (int c = 0; c < 4; ++c) {
        xv[c][0] = *(const float4*)(xsrc + c * 8);
        xv[c][1] = *(const float4*)(xsrc + c * 8 + 4);
    }

    {
        const uint32_t abuf = sb + 32768;
        for (int c = tid; c < 512; c += 256) {
            const int k = c >> 3, dc = c & 7;
            const uint32_t swo = (uint32_t)(k * 128 + ((dc ^ (k & 7)) << 4));
            cp16(abuf + swo, g_Ah + (size_t)k * LD + dc * 8);
            cp16(abuf + 8192 + swo, g_Al + (size_t)k * LD + dc * 8);
        }
        CP_COMMIT;
    }

    float oacc[8][4];
#pragma unroll
    for (int n = 0; n < 8; ++n)
#pragma unroll
        for (int j = 0; j < 4; ++j) oacc[n][j] = 0.0f;

    for (int kt = 0; kt < 16; ++kt) {
        const uint32_t abuf = sb + 32768 + (uint32_t)(kt & 1) * 16384;

#pragma unroll
        for (int c = 0; c < 4; ++c) {
            const int dc = xc0 + c;
            float r0, r1, r2, r3, r4, r5, r6, r7;
            const float h0 = bf_hi_res(xv[c][0].x, r0), h1 = bf_hi_res(xv[c][0].y, r1);
            const float h2 = bf_hi_res(xv[c][0].z, r2), h3 = bf_hi_res(xv[c][0].w, r3);
            const float h4 = bf_hi_res(xv[c][1].x, r4), h5 = bf_hi_res(xv[c][1].y, r5);
            const float h6 = bf_hi_res(xv[c][1].z, r6), h7 = bf_hi_res(xv[c][1].w, r7);
            uint4 ph, pl;
            ph.x = pack_bf16(h0, h1); ph.y = pack_bf16(h2, h3);
            ph.z = pack_bf16(h4, h5); ph.w = pack_bf16(h6, h7);
            pl.x = pack_bf16(r0, r1); pl.y = pack_bf16(r2, r3);
            pl.z = pack_bf16(r4, r5); pl.w = pack_bf16(r6, r7);
            const uint32_t swo = (uint32_t)(xrow * 128 + ((dc ^ (xrow & 7)) << 4));
            *(uint4*)(psm + swo) = ph;
            *(uint4*)(psm + 16384 + swo) = pl;
        }

        if (kt + 1 < 16) {
            const uint32_t anext = sb + 32768 + (uint32_t)((kt + 1) & 1) * 16384;
            const int k0n = (kt + 1) * 64;
            for (int c = tid; c < 512; c += 256) {
                const int k = c >> 3, dc = c & 7;
                const uint32_t swo = (uint32_t)(k * 128 + ((dc ^ (k & 7)) << 4));
                cp16(anext + swo, g_Ah + (size_t)(k0n + k) * LD + dc * 8);
                cp16(anext + 8192 + swo, g_Al + (size_t)(k0n + k) * LD + dc * 8);
            }
            CP_COMMIT;
#pragma unroll
            for (int c = 0; c < 4; ++c) {
                xv[c][0] = *(const float4*)(xsrc + k0n + c * 8);
                xv[c][1] = *(const float4*)(xsrc + k0n + c * 8 + 4);
            }
            CP_WAIT1;
        } else {
            CP_WAIT0;
        }
        __syncthreads();

        const uint32_t xa_base = sb + (uint32_t)((wr + arow) * 128);
#pragma unroll
        for (int ks = 0; ks < 4; ++ks) {
            uint32_t axh[4], axl[4];
            const uint32_t qaddr = xa_base + (uint32_t)((((ks << 1) + acs) ^ l7) << 4);
            ldsm_x4(axh, qaddr);
            ldsm_x4(axl, qaddr + 16384);
            const uint32_t brow = abuf + (uint32_t)((ks * 16 + l15) * 128);
#pragma unroll
            for (int n = 0; n < 8; n += 2) {
                const uint32_t baddr = brow + (uint32_t)(((n + nn_inc) ^ l7) << 4);
                uint32_t bh[4], bl[4];
                ldsm_x4t(bh, baddr);
                ldsm_x4t(bl, baddr + 8192);
                mma_bf16(oacc[n], axh, bh[0], bh[1]);
                mma_bf16(oacc[n], axl, bh[0], bh[1]);
                mma_bf16(oacc[n], axh, bl[0], bl[1]);
                mma_bf16(oacc[n + 1], axh, bh[2], bh[3]);
                mma_bf16(oacc[n + 1], axl, bh[2], bh[3]);
                mma_bf16(oacc[n + 1], axh, bl[2], bl[3]);
            }
        }
        __syncthreads();
    }

    const int row0 = mbase + wr + g;
#pragma unroll
    for (int n = 0; n < 8; ++n) {
        *(float2*)(C + (size_t)row0 * LD + n * 8 + 2 * t) =
            make_float2(oacc[n][0], oacc[n][1]);
        *(float2*)(C + (size_t)(row0 + 8) * LD + n * 8 + 2 * t) =
            make_float2(oacc[n][2], oacc[n][3]);
    }
}

// ---------------------------------------------------------------------------
__global__ __launch_bounds__(256) void colmean_kernel() {
    __shared__ float red[256];
    const int l = blockIdx.x;
    float s = 0.0f;
    for (int r = threadIdx.x; r < NTR; r += 256) s += g_K[(size_t)r * LD + l];
    red[threadIdx.x] = s;
    __syncthreads();
    for (int off = 128; off > 0; off >>= 1) {
        if (threadIdx.x < off) red[threadIdx.x] += red[threadIdx.x + off];
        __syncthreads();
    }
    if (threadIdx.x == 0) g_muA[l] = red[0] * (1.0f / (float)NTR);
}

// ---------------------------------------------------------------------------
// center + bf16 split of Q/K
// ---------------------------------------------------------------------------
__global__ __launch_bounds__(256) void split_qk_kernel() {
    int i = blockIdx.x * 256 + threadIdx.x;
    const bool isQ = (i >= 131072);
    const float* src = isQ ? g_Q : g_K;
    __nv_bfloat16* dh = isQ ? g_Qh : g_Kh;
    __nv_bfloat16* dl = isQ ? g_Ql : g_Kl;
    const int j = isQ ? i - 131072 : i;
    float4 v = ((const float4*)src)[j];
    const int l = (j * 4) & 63;
    v.x -= g_muA[l + 0];
    v.y -= g_muA[l + 1];
    v.z -= g_muA[l + 2];
    v.w -= g_muA[l + 3];
    float r0, r1, r2, r3;
    const float h0 = bf_hi_res(v.x, r0), h1 = bf_hi_res(v.y, r1);
    const float h2 = bf_hi_res(v.z, r2), h3 = bf_hi_res(v.w, r3);
    uint2 ph, pl;
    ph.x = pack_bf16(h0, h1); ph.y = pack_bf16(h2, h3);
    pl.x = pack_bf16(r0, r1); pl.y = pack_bf16(r2, r3);
    ((uint2*)dh)[j] = ph;
    ((uint2*)dl)[j] = pl;
}

// ---------------------------------------------------------------------------
// V split (keeps [key][dy] layout): ytr [8192,128] f32 -> Vh/Vl bf16
// ---------------------------------------------------------------------------
__global__ __launch_bounds__(256) void vsplit_kernel(const float* __restrict__ ytr) {
    const int i = blockIdx.x * 256 + threadIdx.x;
    float4 v = ((const float4*)ytr)[i];
    float r0, r1, r2, r3;
    const float h0 = bf_hi_res(v.x, r0), h1 = bf_hi_res(v.y, r1);
    const float h2 = bf_hi_res(v.z, r2), h3 = bf_hi_res(v.w, r3);
    uint2 ph, pl;
    ph.x = pack_bf16(h0, h1); ph.y = pack_bf16(h2, h3);
    pl.x = pack_bf16(r0, r1); pl.y = pack_bf16(r2, r3);
    ((uint2*)g_Vh)[i] = ph;
    ((uint2*)g_Vl)[i] = pl;
}

// ---------------------------------------------------------------------------
// flash kernel — round-9 pipeline (K double-buffered 2x32KB, V single 64KB,
// V load overlaps QK, next-K overlaps PV) with x4/x4t ldmatrix (THE one change).
// smem total 160KB.
// ---------------------------------------------------------------------------
#define FB_QH 0
#define FB_QL 16384
#define FB_KB 32768
// K buf b at FB_KB + b*32768: KH +0, KL +16384
#define FB_VH 98304
#define FB_VL 131072
#define FSM_BYTES 163840

extern __shared__ char fsm[];

__device__ __forceinline__ void load_K_tile(uint32_t sb, int buf, int kb, int tid) {
    const uint32_t base = sb + FB_KB + (uint32_t)buf * 32768;
    for (int c = tid; c < 1024; c += 256) {
        const int key = c >> 3, dc = c & 7;
        const uint32_t dst = base + key * 128 + ((dc ^ (key & 7)) << 4);
        const size_t gk = ((size_t)(kb + key) << 6) + dc * 8;
        cp16(dst, g_Kh + gk);
        cp16(dst + 16384, g_Kl + gk);
    }
}

__global__ __launch_bounds__(256) void flash_mma_kernel() {
    const int tid = threadIdx.x;
    const int wid = tid >> 5;
    const int lane = tid & 31;
    const int g = lane >> 2;
    const int t = lane & 3;
    const int qblk = blockIdx.x >> 1;
    const int half = blockIdx.x & 1;
    const int qbase = qblk * 128;
    const int wr = wid * 16;
    const uint32_t sb = smem_u32(fsm);

    // ---- prologue: Q tile + K tile 0 in one cp group
    for (int c = tid; c < 1024; c += 256) {
        const int row = c >> 3, dc = c & 7;
        const uint32_t dst = sb + FB_QH + row * 128 + ((dc ^ (row & 7)) << 4);
        const size_t gq = ((size_t)(qbase + row) << 6) + dc * 8;
        cp16(dst, g_Qh + gq);
        cp16(dst + (FB_QL - FB_QH), g_Ql + gq);
    }
    load_K_tile(sb, 0, half * 4096, tid);
    CP_COMMIT;

    const int l7 = lane & 7, l15 = lane & 15;
    const int ab = lane >> 3;
    const int arow = l7 + ((ab & 1) << 3);
    const int acs = ab >> 1;
    const int kcb = (lane >> 3) & 1;       // k-chunk bit (0,1,0,1 per 8 lanes)
    const int nn_inc = (lane >> 4) & 1;    // second-n-tile bit for x4 loads
    const uint32_t qa_base = sb + FB_QH + (uint32_t)(wr + arow) * 128;
    const uint32_t va_base = sb + FB_VH + (uint32_t)l15 * 256;

    float oacc[16][4];
#pragma unroll
    for (int n = 0; n < 16; ++n)
#pragma unroll
        for (int j = 0; j < 4; ++j) oacc[n][j] = 0.0f;
    float rlo = 0.0f, rhi = 0.0f;

    for (int jt = 0; jt < 32; ++jt) {
        const int kb = (half * 32 + jt) * 128;
        const uint32_t kbase = sb + FB_KB + (uint32_t)(jt & 1) * 32768;

        CP_WAIT0;          // K(jt) (and Q on first iter) resident
        __syncthreads();   // also guards V buffer: all PV(jt-1) reads done

        // ---- V(jt) load, overlapped with QK compute
        for (int c = tid; c < 2048; c += 256) {
            const int key = c >> 4, dc = c & 15;
            const uint32_t dst = sb + FB_VH + key * 256 + ((dc ^ (key & 7)) << 4);
            const size_t gv = ((size_t)(kb + key) << 7) + dc * 8;
            cp16(dst, g_Vh + gv);
            cp16(dst + (FB_VL - FB_VH), g_Vl + gv);
        }
        CP_COMMIT;

        // ---- S = Q K^T : x4 non-trans K loads (2 n-tiles per ldmatrix)
        float sacc[16][4];
#pragma unroll
        for (int n = 0; n < 16; ++n)
#pragma unroll
            for (int j = 0; j < 4; ++j) sacc[n][j] = 0.0f;

#pragma unroll
        for (int ks = 0; ks < 4; ++ks) {
            uint32_t aqh[4], aql[4];
            const uint32_t qaddr =
                qa_base + (uint32_t)((((ks << 1) + acs) ^ l7) << 4);
            ldsm_x4(aqh, qaddr);
            ldsm_x4(aql, qaddr + (FB_QL - FB_QH));
            const uint32_t ksw = (uint32_t)((((ks << 1) + kcb) ^ l7) << 4);
#pragma unroll
            for (int n = 0; n < 16; n += 2) {
                const uint32_t kaddr =
                    kbase + (uint32_t)((((n + nn_inc) << 3) + l7) * 128) + ksw;
                uint32_t bh[4], bl[4];
                ldsm_x4(bh, kaddr);
                ldsm_x4(bl, kaddr + 16384);
                mma_bf16(sacc[n], aqh, bh[0], bh[1]);
                mma_bf16(sacc[n], aql, bh[0], bh[1]);
                mma_bf16(sacc[n], aqh, bl[0], bl[1]);
                mma_bf16(sacc[n + 1], aqh, bh[2], bh[3]);
                mma_bf16(sacc[n + 1], aql, bh[2], bh[3]);
                mma_bf16(sacc[n + 1], aqh, bl[2], bl[3]);
            }
        }

        // ---- prefetch K(jt+1) into the other buffer (overlaps exp+PV)
        if (jt + 1 < 32) {
            load_K_tile(sb, (jt + 1) & 1, kb + 128, tid);
            CP_COMMIT;
            CP_WAIT1;      // V(jt) done; K(jt+1) still in flight
        } else {
            CP_WAIT0;      // V(jt) done
        }

        // ---- P = exp(S), pack into A-fragments (hi + lo)
        uint32_t ph[16][2], pl[16][2];
#pragma unroll
        for (int n = 0; n < 16; ++n) {
            const float e0 = __expf(sacc[n][0]);
            const float e1 = __expf(sacc[n][1]);
            const float e2 = __expf(sacc[n][2]);
            const float e3 = __expf(sacc[n][3]);
            rlo += e0 + e1;
            rhi += e2 + e3;
            float r0, r1, r2, r3;
            const float h0 = bf_hi_res(e0, r0), h1 = bf_hi_res(e1, r1);
            const float h2 = bf_hi_res(e2, r2), h3 = bf_hi_res(e3, r3);
            ph[n][0] = pack_bf16(h0, h1);
            ph[n][1] = pack_bf16(h2, h3);
            pl[n][0] = pack_bf16(r0, r1);
            pl[n][1] = pack_bf16(r2, r3);
        }
        __syncthreads();   // V writes visible to all warps' ldmatrix

        // ---- O += P V : x4 trans V loads (2 n-tiles per ldmatrix)
#pragma unroll
        for (int s = 0; s < 8; ++s) {
            const uint32_t ah[4] = {ph[2 * s][0], ph[2 * s][1],
                                    ph[2 * s + 1][0], ph[2 * s + 1][1]};
            const uint32_t al[4] = {pl[2 * s][0], pl[2 * s][1],
                                    pl[2 * s + 1][0], pl[2 * s + 1][1]};
            const uint32_t vsb = va_base + (uint32_t)(s << 12);
#pragma unroll
            for (int n = 0; n < 16; n += 2) {
                const uint32_t vaddr = vsb + (uint32_t)(((n + nn_inc) ^ l7) << 4);
                uint32_t vh[4], vl[4];
                ldsm_x4t(vh, vaddr);
                ldsm_x4t(vl, vaddr + (FB_VL - FB_VH));
                mma_bf16(oacc[n], ah, vh[0], vh[1]);
                mma_bf16(oacc[n], al, vh[0], vh[1]);
                mma_bf16(oacc[n], ah, vl[0], vl[1]);
                mma_bf16(oacc[n + 1], ah, vh[2], vh[3]);
                mma_bf16(oacc[n + 1], al, vh[2], vh[3]);
                mma_bf16(oacc[n + 1], ah, vl[2], vl[3]);
            }
        }
    }

    float* Op = g_Opart + (size_t)half * NT * DY;
    const int row0 = qbase + wr + g;
#pragma unroll
    for (int n = 0; n < 16; ++n) {
        *(float2*)(Op + (size_t)row0 * DY + n * 8 + 2 * t) =
            make_float2(oacc[n][0], oacc[n][1]);
        *(float2*)(Op + (size_t)(row0 + 8) * DY + n * 8 + 2 * t) =
            make_float2(oacc[n][2], oacc[n][3]);
    }
    rlo += __shfl_xor_sync(0xffffffffu, rlo, 1);
    rlo += __shfl_xor_sync(0xffffffffu, rlo, 2);
    rhi += __shfl_xor_sync(0xffffffffu, rhi, 1);
    rhi += __shfl_xor_sync(0xffffffffu, rhi, 2);
    if (t == 0) {
        g_lpart[(size_t)half * NT + row0] = rlo;
        g_lpart[(size_t)half * NT + row0 + 8] = rhi;
    }
}

// ---------------------------------------------------------------------------
// combine: out = (O0 + O1) / (l0 + l1)
// ---------------------------------------------------------------------------
__global__ __launch_bounds__(256) void combine_kernel(float* __restrict__ out) {
    const int i = blockIdx.x * 256 + threadIdx.x;
    const int r = (i * 4) >> 7;
    const float inv = 1.0f / (g_lpart[r] + g_lpart[NT + r]);
    float4 a = ((const float4*)g_Opart)[i];
    float4 b = ((const float4*)(g_Opart + (size_t)NT * DY))[i];
    ((float4*)out)[i] = make_float4((a.x + b.x) * inv, (a.y + b.y) * inv,
                                    (a.z + b.z) * inv, (a.w + b.w) * inv);
}

// ---------------------------------------------------------------------------
extern "C" void kernel_launch(void* const* d_in, const int* in_sizes, int n_in,
                              void* d_out, int out_size) {
    const float* xtr = (const float*)d_in[0];
    const float* ytr = (const float*)d_in[1];
    const float* xt  = (const float*)d_in[2];
    const float* A   = (const float*)d_in[3];
    float* out = (float*)d_out;

    cudaFuncSetAttribute(flash_mma_kernel,
                         cudaFuncAttributeMaxDynamicSharedMemorySize, FSM_BYTES);

    asplit_kernel<<<64, 256>>>(A);
    proj_tc_kernel<<<128, 256>>>(xtr, xt);
    colmean_kernel<<<64, 256>>>();
    split_qk_kernel<<<1024, 256>>>();
    vsplit_kernel<<<1024, 256>>>(ytr);
    flash_mma_kernel<<<128, 256, FSM_BYTES>>>();
    combine_kernel<<<1024, 256>>>(out);
}